// round 2
// baseline (speedup 1.0000x reference)
#include <cuda_runtime.h>

// Key identity: rowsum(softmax(e)) == 1, so the reference reduces to
//   out = alpha * (h @ W_concat) + (1-alpha) * h
// where W_concat[f, h*64+d] = W[h, f, d].  adj is unused by the reference math.
//
// GEMM: M=16384 (B*N), K=256 (F), N=256 (H*D). Fused residual epilogue.

static __device__ float g_Wc[256 * 256];  // W_concat [F=256][H*D=256]

__global__ void prep_W(const float* __restrict__ W) {
    int idx = blockIdx.x * blockDim.x + threadIdx.x;  // 65536
    int f = idx >> 8;
    int n = idx & 255;
    // W layout: [H=4][F=256][D=64]
    g_Wc[idx] = W[((n >> 6) * 256 + f) * 64 + (n & 63)];
}

#define BM 128
#define BN 128
#define BK 16

__global__ __launch_bounds__(256, 2)
void gat_gemm(const float* __restrict__ A,       // h as [16384, 256]
              const float* __restrict__ alpha_p, // scalar on device
              float* __restrict__ out) {
    __shared__ float As[BK][BM];   // transposed A tile
    __shared__ float Bs[BK][BN];

    const int K = 256;
    const int ldA = 256;

    int tid = threadIdx.x;
    int tr = tid >> 4;   // 0..15
    int tc = tid & 15;   // 0..15

    const float* Ablk = A + (size_t)blockIdx.y * BM * ldA;
    const float* Bblk = g_Wc + blockIdx.x * BN;

    float acc[8][8];
    #pragma unroll
    for (int i = 0; i < 8; i++)
        #pragma unroll
        for (int j = 0; j < 8; j++) acc[i][j] = 0.f;

    for (int k0 = 0; k0 < K; k0 += BK) {
        // A tile: 128 rows x 16 k. 512 float4 loads, 2 per thread, store transposed.
        #pragma unroll
        for (int l = 0; l < 2; l++) {
            int id  = tid + l * 256;        // 0..511
            int row = id >> 2;              // 0..127
            int kv  = (id & 3) << 2;        // 0,4,8,12
            float4 v = *reinterpret_cast<const float4*>(Ablk + row * ldA + k0 + kv);
            As[kv + 0][row] = v.x;
            As[kv + 1][row] = v.y;
            As[kv + 2][row] = v.z;
            As[kv + 3][row] = v.w;
        }
        // B tile: 16 k-rows x 128 cols. 512 float4 loads, 2 per thread.
        #pragma unroll
        for (int l = 0; l < 2; l++) {
            int id  = tid + l * 256;
            int row = id >> 5;              // 0..15
            int cv  = (id & 31) << 2;       // 0..124
            *reinterpret_cast<float4*>(&Bs[row][cv]) =
                *reinterpret_cast<const float4*>(Bblk + (k0 + row) * 256 + cv);
        }
        __syncthreads();

        #pragma unroll
        for (int k = 0; k < BK; k++) {
            float a[8], b[8];
            #pragma unroll
            for (int i = 0; i < 8; i++) a[i] = As[k][tr * 8 + i];
            #pragma unroll
            for (int j = 0; j < 8; j++) b[j] = Bs[k][tc * 8 + j];
            #pragma unroll
            for (int i = 0; i < 8; i++)
                #pragma unroll
                for (int j = 0; j < 8; j++)
                    acc[i][j] = fmaf(a[i], b[j], acc[i][j]);
        }
        __syncthreads();
    }

    float alpha = *alpha_p;
    float beta  = 1.0f - alpha;

    int m0 = blockIdx.y * BM + tr * 8;
    int n0 = blockIdx.x * BN + tc * 8;
    #pragma unroll
    for (int i = 0; i < 8; i++) {
        const float* hrow = A   + (size_t)(m0 + i) * ldA + n0;
        float*       orow = out + (size_t)(m0 + i) * ldA + n0;
        #pragma unroll
        for (int jv = 0; jv < 2; jv++) {
            float4 hres = *reinterpret_cast<const float4*>(hrow + jv * 4);
            float4 o;
            o.x = alpha * acc[i][jv * 4 + 0] + beta * hres.x;
            o.y = alpha * acc[i][jv * 4 + 1] + beta * hres.y;
            o.z = alpha * acc[i][jv * 4 + 2] + beta * hres.z;
            o.w = alpha * acc[i][jv * 4 + 3] + beta * hres.w;
            *reinterpret_cast<float4*>(orow + jv * 4) = o;
        }
    }
}

extern "C" void kernel_launch(void* const* d_in, const int* in_sizes, int n_in,
                              void* d_out, int out_size) {
    const float* h       = (const float*)d_in[0];
    // d_in[1] = adj : mathematically unused by the reference
    const float* W       = (const float*)d_in[2];
    const float* alpha_p = (const float*)d_in[3];
    float* out = (float*)d_out;

    prep_W<<<256, 256>>>(W);
    dim3 grid(2, 128);   // N/BN=2, M/BM=128
    gat_gemm<<<grid, 256>>>(h, alpha_p, out);
}

// round 4
// speedup vs baseline: 1.6595x; 1.6595x over previous
#include <cuda_runtime.h>
#include <cuda_bf16.h>
#include <cstdint>

// Identity: rowsum(softmax(e)) == 1  =>  ref == alpha*(h@Wc) + (1-alpha)*h,
// Wc[k, hh*64+d] = W[hh,k,d]; adj unused.
// GEMM M=16384, N=256, K=256 via mma.sync.m16n8k16 bf16 (portable PTX; runs on
// tensor pipe as HMMA on sm_103 base target) with 3-term hi/lo split:
//   A*B ~= Ah*Bh + Ah*Bl + Al*Bh   (fp32 accumulate)

#define BM 128
#define BN 128
#define BK 32
#define KTOT 256
#define NSTAGE 8          // KTOT/BK
#define THREADS 256

// Per-buffer smem: A frags [split2][kt2][mt8][lane32][16B] = 16KB
//                  B frags [split2][kt2][nt16][lane32][8B] = 16KB
#define ABUF_BYTES 16384
#define BUF_BYTES  32768
#define SMEM_TOTAL (2 * BUF_BYTES)

// Pre-fragmented B images (uint32 words), layout:
// idx = nb*16384 + s*2048 + kt*1024 + nt*64 + lane*2 + w
__device__ __align__(16) uint32_t g_Bh[32768];
__device__ __align__(16) uint32_t g_Bl[32768];

__device__ __forceinline__ uint32_t smem_u32(const void* p) {
    uint32_t a;
    asm("{ .reg .u64 t; cvta.to.shared.u64 t, %1; cvt.u32.u64 %0, t; }" : "=r"(a) : "l"(p));
    return a;
}
__device__ __forceinline__ void cp_async16(uint32_t dst, const void* src) {
    asm volatile("cp.async.cg.shared.global [%0], [%1], 16;" :: "r"(dst), "l"(src) : "memory");
}
__device__ __forceinline__ void cp_commit() {
    asm volatile("cp.async.commit_group;" ::: "memory");
}
__device__ __forceinline__ void cp_wait0() {
    asm volatile("cp.async.wait_group 0;" ::: "memory");
}
__device__ __forceinline__ void mma_bf16(float* c, const uint32_t* a, const uint32_t* b) {
    asm volatile(
        "mma.sync.aligned.m16n8k16.row.col.f32.bf16.bf16.f32 "
        "{%0,%1,%2,%3}, {%4,%5,%6,%7}, {%8,%9}, {%0,%1,%2,%3};"
        : "+f"(c[0]), "+f"(c[1]), "+f"(c[2]), "+f"(c[3])
        : "r"(a[0]), "r"(a[1]), "r"(a[2]), "r"(a[3]), "r"(b[0]), "r"(b[1]));
}
__device__ __forceinline__ uint32_t pack_bf16x2(float lo, float hi) {
    __nv_bfloat162 p(__float2bfloat16_rn(lo), __float2bfloat16_rn(hi));
    return *reinterpret_cast<uint32_t*>(&p);
}

// ---------------- prep: split W and lay out B fragments ----------------
__global__ void prep_B(const float* __restrict__ W) {
    int idx = blockIdx.x * 1024 + threadIdx.x;   // 32768 words
    int w    = idx & 1;
    int lane = (idx >> 1) & 31;
    int nt   = (idx >> 6) & 15;
    int kt   = (idx >> 10) & 1;
    int s    = (idx >> 11) & 7;
    int nb   = idx >> 14;
    int g = lane >> 2, t = lane & 3;
    int n = nb * 128 + nt * 8 + g;
    int k = s * 32 + kt * 16 + w * 8 + t * 2;
    // Wc[k][n] = W[n>>6][k][n&63], W strides: (16384, 64, 1)
    float v0 = W[(n >> 6) * 16384 + k * 64 + (n & 63)];
    float v1 = W[(n >> 6) * 16384 + (k + 1) * 64 + (n & 63)];
    float h0 = __bfloat162float(__float2bfloat16_rn(v0));
    float h1 = __bfloat162float(__float2bfloat16_rn(v1));
    g_Bh[idx] = pack_bf16x2(v0, v1);
    g_Bl[idx] = pack_bf16x2(v0 - h0, v1 - h1);
}

// ---------------- main GEMM ----------------
__global__ __launch_bounds__(THREADS, 2)
void gat_mma(const float* __restrict__ A,       // h as [16384][256]
             const float* __restrict__ alpha_p,
             float* __restrict__ out) {
    extern __shared__ char smem[];
    const int tid = threadIdx.x;
    const int lane = tid & 31;
    const int warp = tid >> 5;
    const int warp_m = warp >> 2;   // 0..1
    const int warp_n = warp & 3;    // 0..3
    const int bn = blockIdx.x;      // 0..1
    const int bm0 = blockIdx.y * BM;

    const float* Ablk = A + (size_t)bm0 * KTOT;
    const uint32_t* Bh_blk = g_Bh + bn * 16384;
    const uint32_t* Bl_blk = g_Bl + bn * 16384;

    // staging constants for this thread
    const int sr = tid >> 1;                 // A row 0..127
    const int smt = sr >> 4, sg = sr & 7, shalf = (sr >> 3) & 1;
    const int skqb = (tid & 1) * 4;

    float acc[4][4][4];
    #pragma unroll
    for (int i = 0; i < 4; i++)
        #pragma unroll
        for (int j = 0; j < 4; j++)
            #pragma unroll
            for (int q = 0; q < 4; q++) acc[i][j][q] = 0.f;

    auto stage_load = [&](int s, int buf) {
        char* bb = smem + buf * BUF_BYTES;
        // ---- A: LDG fp32, split hi/lo, store fragment-major ----
        #pragma unroll
        for (int i = 0; i < 4; i++) {
            int kq = skqb + i;
            int kk = kq * 4;
            float4 v = *reinterpret_cast<const float4*>(Ablk + (size_t)sr * KTOT + s * BK + kk);
            float hx = __bfloat162float(__float2bfloat16_rn(v.x));
            float hy = __bfloat162float(__float2bfloat16_rn(v.y));
            float hz = __bfloat162float(__float2bfloat16_rn(v.z));
            float hw = __bfloat162float(__float2bfloat16_rn(v.w));
            uint32_t h01 = pack_bf16x2(v.x, v.y), h23 = pack_bf16x2(v.z, v.w);
            uint32_t l01 = pack_bf16x2(v.x - hx, v.y - hy);
            uint32_t l23 = pack_bf16x2(v.z - hz, v.w - hw);
            int kt = kk >> 4, rem = kk & 15;
            int khalf = rem >> 3, t = (rem & 7) >> 1;
            int w = shalf + 2 * khalf;
            char* pa = bb + (kt * 8 + smt) * 512;
            int l1 = (sg * 4 + t) * 16 + w * 4;
            *reinterpret_cast<uint32_t*>(pa + l1)               = h01;
            *reinterpret_cast<uint32_t*>(pa + l1 + 16)          = h23;
            *reinterpret_cast<uint32_t*>(pa + 8192 + l1)        = l01;
            *reinterpret_cast<uint32_t*>(pa + 8192 + l1 + 16)   = l23;
        }
        // ---- B: raw cp.async copy of pre-fragmented image (16KB) ----
        uint32_t bdst = smem_u32(bb + ABUF_BYTES);
        #pragma unroll
        for (int i = 0; i < 4; i++) {
            int idx = tid + i * THREADS;         // 0..1023
            int split = idx >> 9, j = idx & 511;
            const uint32_t* src = (split ? Bl_blk : Bh_blk) + s * 2048 + j * 4;
            cp_async16(bdst + split * 8192 + j * 16, src);
        }
        cp_commit();
    };

    stage_load(0, 0);

    for (int s = 0; s < NSTAGE; s++) {
        int buf = s & 1;
        cp_wait0();
        __syncthreads();
        if (s + 1 < NSTAGE) stage_load(s + 1, buf ^ 1);

        char* bb = smem + buf * BUF_BYTES;
        #pragma unroll
        for (int kt = 0; kt < 2; kt++) {
            uint32_t bh[4][2], bl[4][2];
            #pragma unroll
            for (int nt = 0; nt < 4; nt++) {
                int ntg = warp_n * 4 + nt;
                uint2 vh = *reinterpret_cast<uint2*>(bb + ABUF_BYTES + (kt * 16 + ntg) * 256 + lane * 8);
                uint2 vl = *reinterpret_cast<uint2*>(bb + ABUF_BYTES + 8192 + (kt * 16 + ntg) * 256 + lane * 8);
                bh[nt][0] = vh.x; bh[nt][1] = vh.y;
                bl[nt][0] = vl.x; bl[nt][1] = vl.y;
            }
            #pragma unroll
            for (int m4 = 0; m4 < 4; m4++) {
                int mt = warp_m * 4 + m4;
                uint4 ahv = *reinterpret_cast<uint4*>(bb + (kt * 8 + mt) * 512 + lane * 16);
                uint4 alv = *reinterpret_cast<uint4*>(bb + 8192 + (kt * 8 + mt) * 512 + lane * 16);
                uint32_t ah[4] = {ahv.x, ahv.y, ahv.z, ahv.w};
                uint32_t al[4] = {alv.x, alv.y, alv.z, alv.w};
                #pragma unroll
                for (int nt = 0; nt < 4; nt++) {
                    mma_bf16(acc[m4][nt], ah, bh[nt]);
                    mma_bf16(acc[m4][nt], ah, bl[nt]);
                    mma_bf16(acc[m4][nt], al, bh[nt]);
                }
            }
        }
    }

    // ---- epilogue: alpha*gemm + (1-alpha)*h ----
    float alpha = *alpha_p;
    float beta = 1.0f - alpha;
    int g = lane >> 2, t = lane & 3;
    #pragma unroll
    for (int m4 = 0; m4 < 4; m4++) {
        int row0 = bm0 + warp_m * 64 + m4 * 16 + g;
        #pragma unroll
        for (int nt = 0; nt < 4; nt++) {
            int col = bn * BN + warp_n * 32 + nt * 8 + t * 2;
            {
                const float* hp = A + (size_t)row0 * KTOT + col;
                float2 hv = *reinterpret_cast<const float2*>(hp);
                float2 o;
                o.x = alpha * acc[m4][nt][0] + beta * hv.x;
                o.y = alpha * acc[m4][nt][1] + beta * hv.y;
                *reinterpret_cast<float2*>(out + (size_t)row0 * KTOT + col) = o;
            }
            {
                const float* hp = A + (size_t)(row0 + 8) * KTOT + col;
                float2 hv = *reinterpret_cast<const float2*>(hp);
                float2 o;
                o.x = alpha * acc[m4][nt][2] + beta * hv.x;
                o.y = alpha * acc[m4][nt][3] + beta * hv.y;
                *reinterpret_cast<float2*>(out + (size_t)(row0 + 8) * KTOT + col) = o;
            }
        }
    }
}

extern "C" void kernel_launch(void* const* d_in, const int* in_sizes, int n_in,
                              void* d_out, int out_size) {
    const float* h       = (const float*)d_in[0];
    // d_in[1] = adj : unused by the reference math
    const float* W       = (const float*)d_in[2];
    const float* alpha_p = (const float*)d_in[3];
    float* out = (float*)d_out;

    cudaFuncSetAttribute(gat_mma, cudaFuncAttributeMaxDynamicSharedMemorySize, SMEM_TOTAL);

    prep_B<<<32, 1024>>>(W);
    dim3 grid(2, 128);
    gat_mma<<<grid, THREADS, SMEM_TOTAL>>>(h, alpha_p, out);
}

// round 10
// speedup vs baseline: 1.7018x; 1.0255x over previous
#include <cuda_runtime.h>
#include <cuda_bf16.h>
#include <cstdint>

// Identity: rowsum(softmax(e)) == 1  =>  ref == alpha*(h@Wc) + (1-alpha)*h,
// Wc[k, hh*64+d] = W[hh,k,d]; adj unused.
// GEMM M=16384, N=256, K=256 via mma.sync.m16n8k16 bf16 with 3-term hi/lo split:
//   A*B ~= Ah*Bh + Ah*Bl + Al*Bh   (fp32 accumulate)
// Software-pipelined A (LDG -> regs overlapped with mma; convert+STS next stage),
// single __syncthreads per stage. (R4 design, re-bench after infra failure.)

#define BM 128
#define BN 128
#define BK 32
#define KTOT 256
#define NSTAGE 8          // KTOT/BK
#define THREADS 256

#define ABUF_BYTES 16384
#define BUF_BYTES  32768
#define SMEM_TOTAL (2 * BUF_BYTES)

// Pre-fragmented B images (uint32 words):
// idx = nb*16384 + s*2048 + kt*1024 + nt*64 + lane*2 + w
__device__ __align__(16) uint32_t g_Bh[32768];
__device__ __align__(16) uint32_t g_Bl[32768];

__device__ __forceinline__ uint32_t smem_u32(const void* p) {
    uint32_t a;
    asm("{ .reg .u64 t; cvta.to.shared.u64 t, %1; cvt.u32.u64 %0, t; }" : "=r"(a) : "l"(p));
    return a;
}
__device__ __forceinline__ void cp_async16(uint32_t dst, const void* src) {
    asm volatile("cp.async.cg.shared.global [%0], [%1], 16;" :: "r"(dst), "l"(src) : "memory");
}
__device__ __forceinline__ void cp_commit() {
    asm volatile("cp.async.commit_group;" ::: "memory");
}
__device__ __forceinline__ void cp_wait0() {
    asm volatile("cp.async.wait_group 0;" ::: "memory");
}
__device__ __forceinline__ void mma_bf16(float* c, const uint32_t* a, const uint32_t* b) {
    asm volatile(
        "mma.sync.aligned.m16n8k16.row.col.f32.bf16.bf16.f32 "
        "{%0,%1,%2,%3}, {%4,%5,%6,%7}, {%8,%9}, {%0,%1,%2,%3};"
        : "+f"(c[0]), "+f"(c[1]), "+f"(c[2]), "+f"(c[3])
        : "r"(a[0]), "r"(a[1]), "r"(a[2]), "r"(a[3]), "r"(b[0]), "r"(b[1]));
}
__device__ __forceinline__ uint32_t pack_bf16x2(float lo, float hi) {
    __nv_bfloat162 p(__float2bfloat16_rn(lo), __float2bfloat16_rn(hi));
    return *reinterpret_cast<uint32_t*>(&p);
}

// ---------------- prep: split W and lay out B fragments ----------------
__global__ void prep_B(const float* __restrict__ W) {
    int idx = blockIdx.x * 1024 + threadIdx.x;   // 32768 words
    int w    = idx & 1;
    int lane = (idx >> 1) & 31;
    int nt   = (idx >> 6) & 15;
    int kt   = (idx >> 10) & 1;
    int s    = (idx >> 11) & 7;
    int nb   = idx >> 14;
    int g = lane >> 2, t = lane & 3;
    int n = nb * 128 + nt * 8 + g;
    int k = s * 32 + kt * 16 + w * 8 + t * 2;
    float v0 = W[(n >> 6) * 16384 + k * 64 + (n & 63)];
    float v1 = W[(n >> 6) * 16384 + (k + 1) * 64 + (n & 63)];
    float h0 = __bfloat162float(__float2bfloat16_rn(v0));
    float h1 = __bfloat162float(__float2bfloat16_rn(v1));
    g_Bh[idx] = pack_bf16x2(v0, v1);
    g_Bl[idx] = pack_bf16x2(v0 - h0, v1 - h1);
}

// ---------------- main GEMM ----------------
__global__ __launch_bounds__(THREADS, 2)
void gat_mma(const float* __restrict__ A,       // h as [16384][256]
             const float* __restrict__ alpha_p,
             float* __restrict__ out) {
    extern __shared__ char smem[];
    const int tid = threadIdx.x;
    const int lane = tid & 31;
    const int warp = tid >> 5;
    const int warp_m = warp >> 2;   // 0..1
    const int warp_n = warp & 3;    // 0..3
    const int bn = blockIdx.x;      // 0..1
    const int bm0 = blockIdx.y * BM;

    const float* Ablk = A + (size_t)bm0 * KTOT;
    const uint32_t* Bh_blk = g_Bh + bn * 16384;
    const uint32_t* Bl_blk = g_Bl + bn * 16384;

    // staging constants for this thread
    const int sr = tid >> 1;                 // A row 0..127
    const int smt = sr >> 4, sg = sr & 7, shalf = (sr >> 3) & 1;
    const int skqb = (tid & 1) * 4;

    float acc[4][4][4];
    #pragma unroll
    for (int i = 0; i < 4; i++)
        #pragma unroll
        for (int j = 0; j < 4; j++)
            #pragma unroll
            for (int q = 0; q < 4; q++) acc[i][j][q] = 0.f;

    float4 va[4];   // staged A row segment (LDG target, consumed by stsA next stage)

    auto ldgA = [&](int s) {
        const float4* p = reinterpret_cast<const float4*>(
            Ablk + (size_t)sr * KTOT + s * BK + skqb * 4);
        #pragma unroll
        for (int i = 0; i < 4; i++) va[i] = p[i];
    };
    auto cpB = [&](int s, int buf) {
        uint32_t bdst = smem_u32(smem + buf * BUF_BYTES + ABUF_BYTES);
        #pragma unroll
        for (int i = 0; i < 4; i++) {
            int idx = tid + i * THREADS;         // 0..1023
            int split = idx >> 9, j = idx & 511;
            const uint32_t* src = (split ? Bl_blk : Bh_blk) + s * 2048 + j * 4;
            cp_async16(bdst + split * 8192 + j * 16, src);
        }
        cp_commit();
    };
    auto stsA = [&](int buf) {
        char* bb = smem + buf * BUF_BYTES;
        #pragma unroll
        for (int i = 0; i < 4; i++) {
            int kk = (skqb + i) * 4;
            float4 v = va[i];
            float hx = __bfloat162float(__float2bfloat16_rn(v.x));
            float hy = __bfloat162float(__float2bfloat16_rn(v.y));
            float hz = __bfloat162float(__float2bfloat16_rn(v.z));
            float hw = __bfloat162float(__float2bfloat16_rn(v.w));
            uint32_t h01 = pack_bf16x2(v.x, v.y), h23 = pack_bf16x2(v.z, v.w);
            uint32_t l01 = pack_bf16x2(v.x - hx, v.y - hy);
            uint32_t l23 = pack_bf16x2(v.z - hz, v.w - hw);
            int kt = kk >> 4, rem = kk & 15;
            int khalf = rem >> 3, t = (rem & 7) >> 1;
            int w = shalf + 2 * khalf;
            char* pa = bb + (kt * 8 + smt) * 512;
            int l1 = (sg * 4 + t) * 16 + w * 4;
            *reinterpret_cast<uint32_t*>(pa + l1)               = h01;
            *reinterpret_cast<uint32_t*>(pa + l1 + 16)          = h23;
            *reinterpret_cast<uint32_t*>(pa + 8192 + l1)        = l01;
            *reinterpret_cast<uint32_t*>(pa + 8192 + l1 + 16)   = l23;
        }
    };

    // prologue: stage 0 A into regs, B into smem buf0
    ldgA(0);
    cpB(0, 0);

    for (int s = 0; s < NSTAGE; s++) {
        int buf = s & 1;
        char* bb = smem + buf * BUF_BYTES;

        stsA(buf);                 // convert+store A(s) (LDG issued 1 stage ago)
        cp_wait0();                // B(s) landed
        __syncthreads();           // STS(s) visible; all reads of other buffers done

        if (s + 1 < NSTAGE) {      // overlap next-stage loads with this stage's mma
            ldgA(s + 1);
            cpB(s + 1, buf ^ 1);
        }

        #pragma unroll
        for (int kt = 0; kt < 2; kt++) {
            // B fragments for this kt
            uint32_t bh[4][2], bl[4][2];
            #pragma unroll
            for (int nt = 0; nt < 4; nt++) {
                int ntg = warp_n * 4 + nt;
                uint2 vh = *reinterpret_cast<uint2*>(bb + ABUF_BYTES + (kt * 16 + ntg) * 256 + lane * 8);
                uint2 vl = *reinterpret_cast<uint2*>(bb + ABUF_BYTES + 8192 + (kt * 16 + ntg) * 256 + lane * 8);
                bh[nt][0] = vh.x; bh[nt][1] = vh.y;
                bl[nt][0] = vl.x; bl[nt][1] = vl.y;
            }
            // prefetch first A fragment to cover LDS latency of the m4 loop head
            uint4 ahv = *reinterpret_cast<uint4*>(bb + (kt * 8 + warp_m * 4) * 512 + lane * 16);
            uint4 alv = *reinterpret_cast<uint4*>(bb + 8192 + (kt * 8 + warp_m * 4) * 512 + lane * 16);
            #pragma unroll
            for (int m4 = 0; m4 < 4; m4++) {
                uint32_t ah[4] = {ahv.x, ahv.y, ahv.z, ahv.w};
                uint32_t al[4] = {alv.x, alv.y, alv.z, alv.w};
                if (m4 + 1 < 4) {
                    int mt = warp_m * 4 + m4 + 1;
                    ahv = *reinterpret_cast<uint4*>(bb + (kt * 8 + mt) * 512 + lane * 16);
                    alv = *reinterpret_cast<uint4*>(bb + 8192 + (kt * 8 + mt) * 512 + lane * 16);
                }
                #pragma unroll
                for (int nt = 0; nt < 4; nt++) {
                    mma_bf16(acc[m4][nt], ah, bh[nt]);
                    mma_bf16(acc[m4][nt], ah, bl[nt]);
                    mma_bf16(acc[m4][nt], al, bh[nt]);
                }
            }
        }
    }

    // ---- epilogue: alpha*gemm + (1-alpha)*h ----
    float alpha = *alpha_p;
    float beta = 1.0f - alpha;
    int g = lane >> 2, t = lane & 3;
    #pragma unroll
    for (int m4 = 0; m4 < 4; m4++) {
        int row0 = bm0 + warp_m * 64 + m4 * 16 + g;
        #pragma unroll
        for (int nt = 0; nt < 4; nt++) {
            int col = bn * BN + warp_n * 32 + nt * 8 + t * 2;
            {
                const float* hp = A + (size_t)row0 * KTOT + col;
                float2 hv = *reinterpret_cast<const float2*>(hp);
                float2 o;
                o.x = alpha * acc[m4][nt][0] + beta * hv.x;
                o.y = alpha * acc[m4][nt][1] + beta * hv.y;
                *reinterpret_cast<float2*>(out + (size_t)row0 * KTOT + col) = o;
            }
            {
                const float* hp = A + (size_t)(row0 + 8) * KTOT + col;
                float2 hv = *reinterpret_cast<const float2*>(hp);
                float2 o;
                o.x = alpha * acc[m4][nt][2] + beta * hv.x;
                o.y = alpha * acc[m4][nt][3] + beta * hv.y;
                *reinterpret_cast<float2*>(out + (size_t)(row0 + 8) * KTOT + col) = o;
            }
        }
    }
}

extern "C" void kernel_launch(void* const* d_in, const int* in_sizes, int n_in,
                              void* d_out, int out_size) {
    const float* h       = (const float*)d_in[0];
    // d_in[1] = adj : unused by the reference math
    const float* W       = (const float*)d_in[2];
    const float* alpha_p = (const float*)d_in[3];
    float* out = (float*)d_out;

    cudaFuncSetAttribute(gat_mma, cudaFuncAttributeMaxDynamicSharedMemorySize, SMEM_TOTAL);

    prep_B<<<32, 1024>>>(W);
    dim3 grid(2, 128);
    gat_mma<<<grid, THREADS, SMEM_TOTAL>>>(h, alpha_p, out);
}

// round 13
// speedup vs baseline: 2.1217x; 1.2467x over previous
#include <cuda_runtime.h>
#include <cuda_bf16.h>
#include <cstdint>

// Identity: rowsum(softmax(e)) == 1  =>  ref == alpha*(h@Wc) + (1-alpha)*h,
// Wc[k, hh*64+d] = W[hh,k,d]; adj unused.
// GEMM M=16384, N=256, K=256 via mma.sync.m16n8k16 bf16, 3-term hi/lo split:
//   A*B ~= Ah*Bh + Ah*Bl + Al*Bh  (fp32 accumulate, rel_err ~3e-6)
// R10: staging is LSU-issue-bound -> pre-convert A and B into stage-contiguous
// fragment-major global images; mainloop uses cp.async.bulk (2 instrs/stage)
// + mbarrier, leaving only consumer LDS + mma in the hot loop.

#define BM 128
#define BN 128
#define BK 32
#define KTOT 256
#define NSTAGE 8
#define THREADS 256

// per stage buffer: A frags 16KB (hi 8KB | lo 8KB) + B frags 16KB (hi | lo)
#define BUF_BYTES 32768
#define SM_MBAR   (2 * BUF_BYTES)
#define SMEM_TOTAL (2 * BUF_BYTES + 64)

// Fragment images, stage-contiguous 16KB chunks (4096 u32) per (block, stage):
//   chunk = [hi 2048 words | lo 2048 words]
// A: word-in-chunk (hi) = ((kt*8+mt)*32 + lane)*4 + w      (16MB total)
// B: word-in-chunk (hi) = kt*1024 + ntg*64 + lane*2 + w    (256KB total)
__device__ __align__(16) uint32_t g_Af[128 * 8 * 4096];
__device__ __align__(16) uint32_t g_Bf[2 * 8 * 4096];

__device__ __forceinline__ uint32_t smem_u32(const void* p) {
    uint32_t a;
    asm("{ .reg .u64 t; cvta.to.shared.u64 t, %1; cvt.u32.u64 %0, t; }" : "=r"(a) : "l"(p));
    return a;
}
__device__ __forceinline__ void mbar_init(uint32_t a, uint32_t cnt) {
    asm volatile("mbarrier.init.shared.b64 [%0], %1;" :: "r"(a), "r"(cnt) : "memory");
}
__device__ __forceinline__ void mbar_expect_tx(uint32_t a, uint32_t tx) {
    asm volatile("mbarrier.arrive.expect_tx.shared.b64 _, [%0], %1;" :: "r"(a), "r"(tx) : "memory");
}
__device__ __forceinline__ void bulk_g2s(uint32_t dst, const void* src, uint32_t bytes, uint32_t mbar) {
    asm volatile("cp.async.bulk.shared::cluster.global.mbarrier::complete_tx::bytes "
                 "[%0], [%1], %2, [%3];"
                 :: "r"(dst), "l"(src), "r"(bytes), "r"(mbar) : "memory");
}
__device__ __forceinline__ void mbar_wait(uint32_t a, uint32_t parity) {
    uint32_t done;
    asm volatile("{ .reg .pred p; mbarrier.try_wait.parity.shared.b64 p, [%1], %2;"
                 " selp.b32 %0,1,0,p; }" : "=r"(done) : "r"(a), "r"(parity) : "memory");
    if (!done) {
        asm volatile("{ .reg .pred P1; WL_%=:"
                     " mbarrier.try_wait.parity.shared.b64 P1, [%0], %1;"
                     " @P1 bra.uni WD_%=; bra.uni WL_%=; WD_%=: }"
                     :: "r"(a), "r"(parity) : "memory");
    }
}
__device__ __forceinline__ void mma_bf16(float* c, const uint32_t* a, const uint32_t* b) {
    asm volatile(
        "mma.sync.aligned.m16n8k16.row.col.f32.bf16.bf16.f32 "
        "{%0,%1,%2,%3}, {%4,%5,%6,%7}, {%8,%9}, {%0,%1,%2,%3};"
        : "+f"(c[0]), "+f"(c[1]), "+f"(c[2]), "+f"(c[3])
        : "r"(a[0]), "r"(a[1]), "r"(a[2]), "r"(a[3]), "r"(b[0]), "r"(b[1]));
}
__device__ __forceinline__ uint32_t pack_bf16x2(float lo, float hi) {
    __nv_bfloat162 p(__float2bfloat16_rn(lo), __float2bfloat16_rn(hi));
    return *reinterpret_cast<uint32_t*>(&p);
}

// ---------------- prep_A: fp32 h -> hi/lo bf16 fragment images ----------------
__global__ __launch_bounds__(256) void prep_A(const float* __restrict__ A) {
    __shared__ float tile[128 * 36];    // padded stride 36 -> conflict-free gather
    const int bm = blockIdx.x, s = blockIdx.y;
    const int tid = threadIdx.x;

    #pragma unroll
    for (int f = 0; f < 4; f++) {
        int lin = tid + f * 256;                  // 0..1023
        int row = lin >> 3, c4 = (lin & 7) * 4;
        float4 v = *reinterpret_cast<const float4*>(
            A + (size_t)(bm * 128 + row) * KTOT + s * BK + c4);
        *reinterpret_cast<float4*>(tile + row * 36 + c4) = v;
    }
    __syncthreads();

    const int mt = tid >> 5, lane = tid & 31;
    const int sg = lane >> 2, t = lane & 3;
    uint32_t* outp = g_Af + (bm * 8 + s) * 4096;
    #pragma unroll
    for (int kt = 0; kt < 2; kt++) {
        uint32_t hw[4], lw[4];
        #pragma unroll
        for (int w = 0; w < 4; w++) {
            int sh = w & 1, kh = w >> 1;
            int row = mt * 16 + sh * 8 + sg;
            int k = kt * 16 + kh * 8 + t * 2;
            float2 v = *reinterpret_cast<float2*>(tile + row * 36 + k);
            float hx = __bfloat162float(__float2bfloat16_rn(v.x));
            float hy = __bfloat162float(__float2bfloat16_rn(v.y));
            hw[w] = pack_bf16x2(v.x, v.y);
            lw[w] = pack_bf16x2(v.x - hx, v.y - hy);
        }
        int wi = ((kt * 8 + mt) * 32 + lane) * 4;
        *reinterpret_cast<uint4*>(outp + wi)        = make_uint4(hw[0], hw[1], hw[2], hw[3]);
        *reinterpret_cast<uint4*>(outp + 2048 + wi) = make_uint4(lw[0], lw[1], lw[2], lw[3]);
    }
}

// ---------------- prep_B: split W and lay out B fragment images ----------------
__global__ void prep_B(const float* __restrict__ W) {
    int idx = blockIdx.x * 1024 + threadIdx.x;   // 32768 hi-words
    int w    = idx & 1;
    int lane = (idx >> 1) & 31;
    int nt   = (idx >> 6) & 15;
    int kt   = (idx >> 10) & 1;
    int s    = (idx >> 11) & 7;
    int nb   = idx >> 14;
    int g = lane >> 2, t = lane & 3;
    int n = nb * 128 + nt * 8 + g;
    int k = s * 32 + kt * 16 + w * 8 + t * 2;
    float v0 = W[(n >> 6) * 16384 + k * 64 + (n & 63)];
    float v1 = W[(n >> 6) * 16384 + (k + 1) * 64 + (n & 63)];
    float h0 = __bfloat162float(__float2bfloat16_rn(v0));
    float h1 = __bfloat162float(__float2bfloat16_rn(v1));
    int base = (nb * 8 + s) * 4096 + kt * 1024 + nt * 64 + lane * 2 + w;
    g_Bf[base]        = pack_bf16x2(v0, v1);
    g_Bf[base + 2048] = pack_bf16x2(v0 - h0, v1 - h1);
}

// ---------------- main GEMM ----------------
__global__ __launch_bounds__(THREADS, 2)
void gat_mma(const float* __restrict__ A,       // h as [16384][256] (epilogue residual)
             const float* __restrict__ alpha_p,
             float* __restrict__ out) {
    extern __shared__ char smem[];
    const uint32_t sb = smem_u32(smem);
    const int tid = threadIdx.x;
    const int lane = tid & 31;
    const int warp = tid >> 5;
    const int warp_m = warp >> 2;   // 0..1
    const int warp_n = warp & 3;    // 0..3
    const int bn = blockIdx.x;      // 0..1
    const int bm0 = blockIdx.y * BM;

    const uint32_t* Asrc = g_Af + (size_t)blockIdx.y * 8 * 4096;
    const uint32_t* Bsrc = g_Bf + (size_t)bn * 8 * 4096;

    if (tid == 0) { mbar_init(sb + SM_MBAR, 1); mbar_init(sb + SM_MBAR + 8, 1); }
    __syncthreads();

    auto issue = [&](int s, int buf) {
        if (tid == 0) {
            uint32_t mb = sb + SM_MBAR + buf * 8;
            mbar_expect_tx(mb, 2 * 16384);
            bulk_g2s(sb + buf * BUF_BYTES,         Asrc + s * 4096, 16384, mb);
            bulk_g2s(sb + buf * BUF_BYTES + 16384, Bsrc + s * 4096, 16384, mb);
        }
    };

    issue(0, 0);
    issue(1, 1);

    float acc[4][4][4];
    #pragma unroll
    for (int i = 0; i < 4; i++)
        #pragma unroll
        for (int j = 0; j < 4; j++)
            #pragma unroll
            for (int q = 0; q < 4; q++) acc[i][j][q] = 0.f;

    for (int s = 0; s < NSTAGE; s++) {
        int buf = s & 1;
        int ph = (s >> 1) & 1;
        char* bb = smem + buf * BUF_BYTES;

        mbar_wait(sb + SM_MBAR + buf * 8, ph);

        #pragma unroll
        for (int kt = 0; kt < 2; kt++) {
            uint32_t bh[4][2], bl[4][2];
            #pragma unroll
            for (int nt = 0; nt < 4; nt++) {
                int ntg = warp_n * 4 + nt;
                uint2 vh = *reinterpret_cast<uint2*>(bb + 16384 + (kt * 16 + ntg) * 256 + lane * 8);
                uint2 vl = *reinterpret_cast<uint2*>(bb + 16384 + 8192 + (kt * 16 + ntg) * 256 + lane * 8);
                bh[nt][0] = vh.x; bh[nt][1] = vh.y;
                bl[nt][0] = vl.x; bl[nt][1] = vl.y;
            }
            uint4 ahv = *reinterpret_cast<uint4*>(bb + (kt * 8 + warp_m * 4) * 512 + lane * 16);
            uint4 alv = *reinterpret_cast<uint4*>(bb + 8192 + (kt * 8 + warp_m * 4) * 512 + lane * 16);
            #pragma unroll
            for (int m4 = 0; m4 < 4; m4++) {
                uint32_t ah[4] = {ahv.x, ahv.y, ahv.z, ahv.w};
                uint32_t al[4] = {alv.x, alv.y, alv.z, alv.w};
                if (m4 + 1 < 4) {
                    int mt = warp_m * 4 + m4 + 1;
                    ahv = *reinterpret_cast<uint4*>(bb + (kt * 8 + mt) * 512 + lane * 16);
                    alv = *reinterpret_cast<uint4*>(bb + 8192 + (kt * 8 + mt) * 512 + lane * 16);
                }
                #pragma unroll
                for (int nt = 0; nt < 4; nt++) {
                    mma_bf16(acc[m4][nt], ah, bh[nt]);
                    mma_bf16(acc[m4][nt], ah, bl[nt]);
                    mma_bf16(acc[m4][nt], al, bh[nt]);
                }
            }
        }

        __syncthreads();                 // all warps done reading buf
        if (s + 2 < NSTAGE) issue(s + 2, buf);
    }

    // ---- epilogue: alpha*gemm + (1-alpha)*h ----
    float alpha = *alpha_p;
    float beta = 1.0f - alpha;
    int g = lane >> 2, t = lane & 3;
    #pragma unroll
    for (int m4 = 0; m4 < 4; m4++) {
        int row0 = bm0 + warp_m * 64 + m4 * 16 + g;
        #pragma unroll
        for (int nt = 0; nt < 4; nt++) {
            int col = bn * BN + warp_n * 32 + nt * 8 + t * 2;
            {
                float2 hv = *reinterpret_cast<const float2*>(A + (size_t)row0 * KTOT + col);
                float2 o;
                o.x = alpha * acc[m4][nt][0] + beta * hv.x;
                o.y = alpha * acc[m4][nt][1] + beta * hv.y;
                *reinterpret_cast<float2*>(out + (size_t)row0 * KTOT + col) = o;
            }
            {
                float2 hv = *reinterpret_cast<const float2*>(A + (size_t)(row0 + 8) * KTOT + col);
                float2 o;
                o.x = alpha * acc[m4][nt][2] + beta * hv.x;
                o.y = alpha * acc[m4][nt][3] + beta * hv.y;
                *reinterpret_cast<float2*>(out + (size_t)(row0 + 8) * KTOT + col) = o;
            }
        }
    }
}

extern "C" void kernel_launch(void* const* d_in, const int* in_sizes, int n_in,
                              void* d_out, int out_size) {
    const float* h       = (const float*)d_in[0];
    // d_in[1] = adj : unused by the reference math
    const float* W       = (const float*)d_in[2];
    const float* alpha_p = (const float*)d_in[3];
    float* out = (float*)d_out;

    cudaFuncSetAttribute(gat_mma, cudaFuncAttributeMaxDynamicSharedMemorySize, SMEM_TOTAL);

    prep_B<<<32, 1024>>>(W);
    dim3 gA(128, 8);
    prep_A<<<gA, 256>>>(h);
    dim3 grid(2, 128);
    gat_mma<<<grid, THREADS, SMEM_TOTAL>>>(h, alpha_p, out);
}